// round 15
// baseline (speedup 1.0000x reference)
#include <cuda_runtime.h>
#include <stdint.h>

// out[i] = in[i] + 0.1*sqrt(2)*erfinv(u(i)), matching
// jax.random.normal(jax.random.key(42), (64,3,512,512), f32),
// jax_threefry_partitionable=True:
//   (y0,y1) = threefry2x32((0,42),(0,i));  bits = y0 ^ y1
//   u = fma(float_rd(bits), 2^-31, LO), LO=-0.99999994
//   noise = 0.1*sqrt(2)*erfinv(u); Giles poly evaluated directly in
//   L = lg2(1-u^2) (central branch deg 3, scale folded).
//
// Calibrated model: alu pipe carries exactly the irreducible 41 SHF/LOP3/XOR
// ops per element at 86% duty; issue at 80%. This round: two-phase body
// (all 8 integer hash chains first, then fp) + __launch_bounds__(256,2) so
// ptxas can keep all 8 chains in flight (was ~2 at 42 regs), closing the
// exposed-RAW-latency gap in issue.

// 20-round threefry2x32 on (0, ctr), v = ctr + 42 (key-injection 0 applied).
// Returns x0 ^ x1 after the final injection.
__device__ __forceinline__ uint32_t tf_bits(uint32_t v) {
#define TF_RND(r) { x0 += x1; x1 = __funnelshift_l(x1, x1, (r)) ^ x0; }
    uint32_t x0 = v;
    uint32_t x1 = __funnelshift_l(v, v, 13) ^ v;   // round 1 (x0 was 0)
    TF_RND(15) TF_RND(26) TF_RND(6)
    x1 += 0x1BD11BF1u;                      // inj1: k2+1
    x0 = x0 + 42u + x1;
    x1 = __funnelshift_l(x1, x1, 17) ^ x0;
    TF_RND(29) TF_RND(16) TF_RND(24)
    x1 += 2u;                               // inj2
    x0 = x0 + 0x1BD11BF0u + x1;
    x1 = __funnelshift_l(x1, x1, 13) ^ x0;
    TF_RND(15) TF_RND(26) TF_RND(6)
    x1 += 45u;                              // inj3 (k0=0 side free)
    x0 = x0 + x1;
    x1 = __funnelshift_l(x1, x1, 17) ^ x0;
    TF_RND(29) TF_RND(16) TF_RND(24)
    x1 += 0x1BD11BF4u;                      // inj4: k2+4
    x0 = x0 + 42u + x1;
    x1 = __funnelshift_l(x1, x1, 13) ^ x0;
    TF_RND(15) TF_RND(26) TF_RND(6)
    return (x0 + 0x1BD11BF0u) ^ (x1 + 5u);  // final injection + lane XOR
#undef TF_RND
}

// bits -> u in [LO, 1): round-DOWN I2F keeps u < 1 strictly (no lg2 NaN).
__device__ __forceinline__ float bits_to_u(uint32_t y) {
    return fmaf(__uint2float_rd(y), 4.656612873e-10f /* 2^-31 */,
                -0.99999994f);
}

// Rare tail (L <= -7.2134752, i.e. w >= 5): full Giles tail poly,
// 0.1*sqrt(2) folded. L = lg2(1-u^2).
__device__ __forceinline__ float noise_tail_L(float L, float u) {
    float w = -0.693147181f * L;
    float s = sqrtf(w) - 3.0f;
    float p =       -2.83145467e-05f;
    p = fmaf(p, s,   1.42766481e-05f);
    p = fmaf(p, s,   1.90824894e-04f);
    p = fmaf(p, s,  -5.19499916e-04f);
    p = fmaf(p, s,   8.11690563e-04f);
    p = fmaf(p, s,  -1.07798485e-03f);
    p = fmaf(p, s,   1.33486521e-03f);
    p = fmaf(p, s,   1.41657794e-01f);
    p = fmaf(p, s,   4.00644237e-01f);
    return p * u;
}

// Central branch: deg-3 poly in L (exact transform of Giles central poly,
// deg-4 term dropped; 0.1*sqrt(2) folded). noise = q(L)*u.
#define Q3  5.9046144e-5f
#define Q2  3.5503370e-4f
#define Q1 -2.39205466e-2f
#define Q0  1.24209004e-1f
#define L_TAIL -7.2134752f

// Guard-free kernel: 8 elements/thread, grid*block*8 == n exactly.
// min-blocks hint 2 -> ptxas may use up to ~128 regs: all 8 hash chains
// can stay in flight during the integer phase.
__global__ void __launch_bounds__(256, 2)
noise_vec8_exact(const float4* __restrict__ in, float4* __restrict__ out) {
    int tid = blockIdx.x * blockDim.x + threadIdx.x;
    float4 a0 = in[2 * tid];
    float4 a1 = in[2 * tid + 1];
    const float av[8] = {a0.x, a0.y, a0.z, a0.w, a1.x, a1.y, a1.z, a1.w};
    uint32_t c42 = 8u * (uint32_t)tid + 42u;     // ctr + key-injection 0

    // Phase 1: 8 independent integer hash chains.
    uint32_t y[8];
#pragma unroll
    for (int j = 0; j < 8; j++)
        y[j] = tf_bits(c42 + (uint32_t)j);

    // Phase 2: fp pipeline.
    float u[8], Ls[8], o[8];
#pragma unroll
    for (int j = 0; j < 8; j++) {
        float uu = bits_to_u(y[j]);
        float g = fmaf(-uu, uu, 1.0f);                // 1 - u^2, > 0
        float L;
        asm("lg2.approx.f32 %0, %1;" : "=f"(L) : "f"(g));
        float q = fmaf(Q3, L, Q2);
        q = fmaf(q, L, Q1);
        q = fmaf(q, L, Q0);
        u[j] = uu; Ls[j] = L;
        o[j] = fmaf(q, uu, av[j]);                    // out = a + q*u, fused
    }

    // One branch per thread for the rare tail (P ~ 2.7%/thread).
    float m01 = fminf(Ls[0], Ls[1]), m23 = fminf(Ls[2], Ls[3]);
    float m45 = fminf(Ls[4], Ls[5]), m67 = fminf(Ls[6], Ls[7]);
    float mn = fminf(fminf(m01, m23), fminf(m45, m67));
    if (mn <= L_TAIL) {
#pragma unroll
        for (int j = 0; j < 8; j++)
            if (Ls[j] <= L_TAIL) o[j] = av[j] + noise_tail_L(Ls[j], u[j]);
    }

    float4 r0, r1;
    r0.x = o[0]; r0.y = o[1]; r0.z = o[2]; r0.w = o[3];
    r1.x = o[4]; r1.y = o[5]; r1.z = o[6]; r1.w = o[7];
    out[2 * tid]     = r0;
    out[2 * tid + 1] = r1;
}

// 4-elem guarded fallback (used only if n doesn't split into exact 8x grid).
__global__ void __launch_bounds__(256)
noise_vec4_guard(const float4* __restrict__ in, float4* __restrict__ out,
                 int start4, int n4) {
    int tid = start4 + blockIdx.x * blockDim.x + threadIdx.x;
    if (tid >= n4) return;
    float4 a = in[tid];
    const float av[4] = {a.x, a.y, a.z, a.w};
    uint32_t c42 = 4u * (uint32_t)tid + 42u;
    float u[4], Ls[4], o[4];
#pragma unroll
    for (int j = 0; j < 4; j++) {
        uint32_t yj = tf_bits(c42 + (uint32_t)j);
        float uu = bits_to_u(yj);
        float g = fmaf(-uu, uu, 1.0f);
        float L;
        asm("lg2.approx.f32 %0, %1;" : "=f"(L) : "f"(g));
        float q = fmaf(Q3, L, Q2);
        q = fmaf(q, L, Q1);
        q = fmaf(q, L, Q0);
        u[j] = uu; Ls[j] = L;
        o[j] = fmaf(q, uu, av[j]);
    }
    float mn = fminf(fminf(Ls[0], Ls[1]), fminf(Ls[2], Ls[3]));
    if (mn <= L_TAIL) {
#pragma unroll
        for (int j = 0; j < 4; j++)
            if (Ls[j] <= L_TAIL) o[j] = av[j] + noise_tail_L(Ls[j], u[j]);
    }
    float4 r;
    r.x = o[0]; r.y = o[1]; r.z = o[2]; r.w = o[3];
    out[tid] = r;
}

// Scalar fallback for n % 4 != 0 (not hit for this shape).
__global__ void noise_scalar_kernel(const float* __restrict__ in,
                                    float* __restrict__ out,
                                    unsigned int start, unsigned int n) {
    unsigned int i = start + blockIdx.x * blockDim.x + threadIdx.x;
    if (i >= n) return;
    uint32_t y = tf_bits(i + 42u);
    float u = bits_to_u(y);
    float g = fmaf(-u, u, 1.0f);
    float L;
    asm("lg2.approx.f32 %0, %1;" : "=f"(L) : "f"(g));
    float q = fmaf(Q3, L, Q2);
    q = fmaf(q, L, Q1);
    q = fmaf(q, L, Q0);
    float nz = (L > L_TAIL) ? q * u : noise_tail_L(L, u);
    out[i] = in[i] + nz;
}

extern "C" void kernel_launch(void* const* d_in, const int* in_sizes, int n_in,
                              void* d_out, int out_size) {
    const float* in = (const float*)d_in[0];
    float* out = (float*)d_out;

    unsigned int n = (unsigned int)in_sizes[0];  // 50331648
    const int threads = 256;

    unsigned int n8 = n / 8u;                    // 6291456 = 24576 * 256
    unsigned int done = 0;
    if (n8 >= (unsigned int)threads && (n8 % threads) == 0) {
        noise_vec8_exact<<<n8 / threads, threads>>>((const float4*)in,
                                                    (float4*)out);
        done = n8 * 8u;
    }
    unsigned int n4 = n / 4u;
    unsigned int start4 = done / 4u;
    if (start4 < n4) {
        unsigned int rem4 = n4 - start4;
        noise_vec4_guard<<<(rem4 + threads - 1) / threads, threads>>>(
            (const float4*)in, (float4*)out, (int)start4, (int)n4);
        done = n4 * 4u;
    }
    if (done < n) {
        unsigned int rem = n - done;
        noise_scalar_kernel<<<(rem + 255) / 256, 256>>>(in, out, done, n);
    }
}

// round 16
// speedup vs baseline: 1.0137x; 1.0137x over previous
#include <cuda_runtime.h>
#include <stdint.h>

// out[i] = in[i] + 0.1*sqrt(2)*erfinv(u(i)), matching
// jax.random.normal(jax.random.key(42), (64,3,512,512), f32),
// jax_threefry_partitionable=True:
//   (y0,y1) = threefry2x32((0,42),(0,i));  bits = y0 ^ y1
//   u = fma(float_rd(bits), 2^-31, LO), LO=-0.99999994
//   noise = 0.1*sqrt(2)*erfinv(u); Giles poly evaluated directly in
//   L = lg2(1-u^2) (central branch deg 3, scale folded).
//
// Calibrated: alu pipe = exactly 41 irreducible ops/elem at 86% duty; the
// remaining 14% alu idle is per-warp RAW exposure (only ~2 hash chains live
// at 43 regs). This round: 16 elements/thread so ptxas must keep more
// chains in flight; per-thread overhead amortizes 2x. Occupancy is spent
// deliberately (evidence: occ 55-88% all gave issue ~80%).

// 20-round threefry2x32 on (0, ctr), v = ctr + 42 (key-injection 0 applied).
__device__ __forceinline__ uint32_t tf_bits(uint32_t v) {
#define TF_RND(r) { x0 += x1; x1 = __funnelshift_l(x1, x1, (r)) ^ x0; }
    uint32_t x0 = v;
    uint32_t x1 = __funnelshift_l(v, v, 13) ^ v;   // round 1 (x0 was 0)
    TF_RND(15) TF_RND(26) TF_RND(6)
    x1 += 0x1BD11BF1u;                      // inj1: k2+1
    x0 = x0 + 42u + x1;
    x1 = __funnelshift_l(x1, x1, 17) ^ x0;
    TF_RND(29) TF_RND(16) TF_RND(24)
    x1 += 2u;                               // inj2
    x0 = x0 + 0x1BD11BF0u + x1;
    x1 = __funnelshift_l(x1, x1, 13) ^ x0;
    TF_RND(15) TF_RND(26) TF_RND(6)
    x1 += 45u;                              // inj3
    x0 = x0 + x1;
    x1 = __funnelshift_l(x1, x1, 17) ^ x0;
    TF_RND(29) TF_RND(16) TF_RND(24)
    x1 += 0x1BD11BF4u;                      // inj4: k2+4
    x0 = x0 + 42u + x1;
    x1 = __funnelshift_l(x1, x1, 13) ^ x0;
    TF_RND(15) TF_RND(26) TF_RND(6)
    return (x0 + 0x1BD11BF0u) ^ (x1 + 5u);  // final injection + lane XOR
#undef TF_RND
}

// bits -> u in [LO, 1): round-DOWN I2F keeps u < 1 strictly (no lg2 NaN).
__device__ __forceinline__ float bits_to_u(uint32_t y) {
    return fmaf(__uint2float_rd(y), 4.656612873e-10f /* 2^-31 */,
                -0.99999994f);
}

// Rare tail (L <= -7.2134752, i.e. w >= 5): full Giles tail poly,
// 0.1*sqrt(2) folded. L = lg2(1-u^2).
__device__ __forceinline__ float noise_tail_L(float L, float u) {
    float w = -0.693147181f * L;
    float s = sqrtf(w) - 3.0f;
    float p =       -2.83145467e-05f;
    p = fmaf(p, s,   1.42766481e-05f);
    p = fmaf(p, s,   1.90824894e-04f);
    p = fmaf(p, s,  -5.19499916e-04f);
    p = fmaf(p, s,   8.11690563e-04f);
    p = fmaf(p, s,  -1.07798485e-03f);
    p = fmaf(p, s,   1.33486521e-03f);
    p = fmaf(p, s,   1.41657794e-01f);
    p = fmaf(p, s,   4.00644237e-01f);
    return p * u;
}

// Central branch: deg-3 poly in L (exact transform of Giles central poly,
// deg-4 term dropped; 0.1*sqrt(2) folded). noise = q(L)*u.
#define Q3  5.9046144e-5f
#define Q2  3.5503370e-4f
#define Q1 -2.39205466e-2f
#define Q0  1.24209004e-1f
#define L_TAIL -7.2134752f

// Guard-free kernel: 16 elements/thread, grid*block*16 == n exactly.
__global__ void __launch_bounds__(256)
noise_vec16_exact(const float4* __restrict__ in, float4* __restrict__ out) {
    int tid = blockIdx.x * blockDim.x + threadIdx.x;

    float4 a[4];
#pragma unroll
    for (int k = 0; k < 4; k++) a[k] = in[4 * tid + k];
    const float* av = &a[0].x;

    uint32_t c42 = 16u * (uint32_t)tid + 42u;    // ctr + key-injection 0

    // Phase 1: 16 independent integer hash chains.
    uint32_t y[16];
#pragma unroll
    for (int j = 0; j < 16; j++)
        y[j] = tf_bits(c42 + (uint32_t)j);

    // Phase 2: fp pipeline.
    float u[16], Ls[16], o[16];
#pragma unroll
    for (int j = 0; j < 16; j++) {
        float uu = bits_to_u(y[j]);
        float g = fmaf(-uu, uu, 1.0f);                // 1 - u^2, > 0
        float L;
        asm("lg2.approx.f32 %0, %1;" : "=f"(L) : "f"(g));
        float q = fmaf(Q3, L, Q2);
        q = fmaf(q, L, Q1);
        q = fmaf(q, L, Q0);
        u[j] = uu; Ls[j] = L;
        o[j] = fmaf(q, uu, av[j]);                    // out = a + q*u, fused
    }

    // One branch per thread for the rare tail (P ~ 5.4%/thread).
    float mn = Ls[0];
#pragma unroll
    for (int j = 1; j < 16; j++) mn = fminf(mn, Ls[j]);
    if (mn <= L_TAIL) {
#pragma unroll
        for (int j = 0; j < 16; j++)
            if (Ls[j] <= L_TAIL) o[j] = av[j] + noise_tail_L(Ls[j], u[j]);
    }

#pragma unroll
    for (int k = 0; k < 4; k++) {
        float4 r;
        r.x = o[4 * k]; r.y = o[4 * k + 1];
        r.z = o[4 * k + 2]; r.w = o[4 * k + 3];
        out[4 * tid + k] = r;
    }
}

// 4-elem guarded fallback (used only if n doesn't split into exact 16x grid).
__global__ void __launch_bounds__(256)
noise_vec4_guard(const float4* __restrict__ in, float4* __restrict__ out,
                 int start4, int n4) {
    int tid = start4 + blockIdx.x * blockDim.x + threadIdx.x;
    if (tid >= n4) return;
    float4 a = in[tid];
    const float av[4] = {a.x, a.y, a.z, a.w};
    uint32_t c42 = 4u * (uint32_t)tid + 42u;
    float u[4], Ls[4], o[4];
#pragma unroll
    for (int j = 0; j < 4; j++) {
        uint32_t yj = tf_bits(c42 + (uint32_t)j);
        float uu = bits_to_u(yj);
        float g = fmaf(-uu, uu, 1.0f);
        float L;
        asm("lg2.approx.f32 %0, %1;" : "=f"(L) : "f"(g));
        float q = fmaf(Q3, L, Q2);
        q = fmaf(q, L, Q1);
        q = fmaf(q, L, Q0);
        u[j] = uu; Ls[j] = L;
        o[j] = fmaf(q, uu, av[j]);
    }
    float mn = fminf(fminf(Ls[0], Ls[1]), fminf(Ls[2], Ls[3]));
    if (mn <= L_TAIL) {
#pragma unroll
        for (int j = 0; j < 4; j++)
            if (Ls[j] <= L_TAIL) o[j] = av[j] + noise_tail_L(Ls[j], u[j]);
    }
    float4 r;
    r.x = o[0]; r.y = o[1]; r.z = o[2]; r.w = o[3];
    out[tid] = r;
}

// Scalar fallback for n % 4 != 0 (not hit for this shape).
__global__ void noise_scalar_kernel(const float* __restrict__ in,
                                    float* __restrict__ out,
                                    unsigned int start, unsigned int n) {
    unsigned int i = start + blockIdx.x * blockDim.x + threadIdx.x;
    if (i >= n) return;
    uint32_t y = tf_bits(i + 42u);
    float u = bits_to_u(y);
    float g = fmaf(-u, u, 1.0f);
    float L;
    asm("lg2.approx.f32 %0, %1;" : "=f"(L) : "f"(g));
    float q = fmaf(Q3, L, Q2);
    q = fmaf(q, L, Q1);
    q = fmaf(q, L, Q0);
    float nz = (L > L_TAIL) ? q * u : noise_tail_L(L, u);
    out[i] = in[i] + nz;
}

extern "C" void kernel_launch(void* const* d_in, const int* in_sizes, int n_in,
                              void* d_out, int out_size) {
    const float* in = (const float*)d_in[0];
    float* out = (float*)d_out;

    unsigned int n = (unsigned int)in_sizes[0];  // 50331648
    const int threads = 256;

    unsigned int n16 = n / 16u;                  // 3145728 = 12288 * 256
    unsigned int done = 0;
    if (n16 >= (unsigned int)threads && (n16 % threads) == 0) {
        noise_vec16_exact<<<n16 / threads, threads>>>((const float4*)in,
                                                      (float4*)out);
        done = n16 * 16u;
    }
    unsigned int n4 = n / 4u;
    unsigned int start4 = done / 4u;
    if (start4 < n4) {
        unsigned int rem4 = n4 - start4;
        noise_vec4_guard<<<(rem4 + threads - 1) / threads, threads>>>(
            (const float4*)in, (float4*)out, (int)start4, (int)n4);
        done = n4 * 4u;
    }
    if (done < n) {
        unsigned int rem = n - done;
        noise_scalar_kernel<<<(rem + 255) / 256, 256>>>(in, out, done, n);
    }
}